// round 14
// baseline (speedup 1.0000x reference)
#include <cuda_runtime.h>
#include <cstdint>

// Problem constants
#define BB  16
#define CC  256
#define HW  4096
#define EE  4
#define HID 128
#define RHD 128

// ---------------- device-global scratch (allowed; no dynamic alloc) ----------
__device__ __align__(16) float g_pooled[BB * CC];
__device__ int   g_expert[BB];
__device__ float g_weight[BB];
__device__ __align__(16) float g_y1[(size_t)BB * HID * HW];    // tf32-rounded
__device__ __align__(16) float g_y2[(size_t)BB * HID * HW];    // tf32-rounded
__device__ __align__(16) float g_xr[(size_t)BB * CC * HW];     // tf32-rounded x
__device__ __align__(16) float g_w1r[EE * HID * CC];
__device__ __align__(16) float g_w2r[EE * HID * HID * 9];
__device__ __align__(16) float g_w3r[EE * CC * HID];

__device__ __forceinline__ float to_tf32(float x) {
    float r; asm("cvt.rna.tf32.f32 %0, %1;" : "=f"(r) : "f"(x)); return r;
}

// m16n8k8 tf32 mma (arch-agnostic PTX, works on plain sm_103 target)
__device__ __forceinline__ void mma_tf32(float* d,
                                         uint32_t a0, uint32_t a1, uint32_t a2, uint32_t a3,
                                         uint32_t b0, uint32_t b1) {
    asm volatile(
        "mma.sync.aligned.m16n8k8.row.col.f32.tf32.tf32.f32 "
        "{%0,%1,%2,%3}, {%4,%5,%6,%7}, {%8,%9}, {%0,%1,%2,%3};"
        : "+f"(d[0]), "+f"(d[1]), "+f"(d[2]), "+f"(d[3])
        : "r"(a0), "r"(a1), "r"(a2), "r"(a3), "r"(b0), "r"(b1));
}

// ---------------- cp.async helpers ------------------------------------------
__device__ __forceinline__ uint32_t cvta_s(const void* p) {
    return (uint32_t)__cvta_generic_to_shared(p);
}
__device__ __forceinline__ void cp16(uint32_t dst, const void* src) {
    asm volatile("cp.async.cg.shared.global [%0], [%1], 16;" :: "r"(dst), "l"(src));
}
__device__ __forceinline__ void cp4(uint32_t dst, const void* src, uint32_t ssz) {
    asm volatile("cp.async.ca.shared.global [%0], [%1], 4, %2;" :: "r"(dst), "l"(src), "r"(ssz));
}
__device__ __forceinline__ void cp_commit()   { asm volatile("cp.async.commit_group;" ::: "memory"); }
template<int N>
__device__ __forceinline__ void cp_wait_group() {
    asm volatile("cp.async.wait_group %0;" :: "n"(N) : "memory");
}

// ============================================================================
// SMEM layouts per 32-K chunk (4096 floats each = 16 KB):
//  A word((m,k)) = ((mt*4+ks)*4 + rgA)*32 + (m&7)*4 + (k&3)
//  B word((n,k)) = ((nt*4+ks)*2 + rg)*32 + (fl ^ swz(nt)),  fl=(k&3)*8+(n&7)
//      GEMM swz = (nt&3)*8 ;  CONV swz = (nt&3) | ((nt&4)<<2)
// Triple buffer: buffer i at byte offset i*32768; B at +16384 within buffer.
// ============================================================================

template<int CONV>
__device__ __forceinline__ void mma_chunk(const float* sA, const float* sB,
                                          int warpm, int warpn, int lane,
                                          float acc[2][8][4]) {
    const int fl0 = (lane & 3) * 8 + (lane >> 2);
    #pragma unroll
    for (int ks = 0; ks < 4; ks++) {
        uint32_t a[2][4];
        #pragma unroll
        for (int mt2 = 0; mt2 < 2; mt2++) {
            const float* pa = sA + ((warpm * 2 + mt2) * 4 + ks) * 128 + lane;
            a[mt2][0] = __float_as_uint(pa[0]);
            a[mt2][1] = __float_as_uint(pa[32]);
            a[mt2][2] = __float_as_uint(pa[64]);
            a[mt2][3] = __float_as_uint(pa[96]);
        }
        // software-pipelined B fragments (one nt ahead of the MMAs)
        auto ldb = [&](int nt2, uint32_t& b0, uint32_t& b1) {
            int nt  = warpn * 8 + nt2;
            int swz = CONV ? ((nt & 3) | ((nt & 4) << 2)) : ((nt & 3) * 8);
            int fx  = fl0 ^ swz;
            const float* pb = sB + (nt * 4 + ks) * 64;
            b0 = __float_as_uint(pb[fx]);
            b1 = __float_as_uint(pb[32 + fx]);
        };
        uint32_t b0c, b1c, b0n, b1n;
        ldb(0, b0c, b1c);
        #pragma unroll
        for (int nt2 = 0; nt2 < 8; nt2++) {
            if (nt2 < 7) ldb(nt2 + 1, b0n, b1n);
            mma_tf32(acc[0][nt2], a[0][0], a[0][1], a[0][2], a[0][3], b0c, b1c);
            mma_tf32(acc[1][nt2], a[1][0], a[1][1], a[1][2], a[1][3], b0c, b1c);
            b0c = b0n; b1c = b1n;
        }
    }
}

// ============================================================================
// Kernel 1: global average pool + tf32-round x into g_xr. grid=B*C, 256 thr.
// ============================================================================
__global__ void pool_round_kernel(const float* __restrict__ x) {
    int bc = blockIdx.x;
    const float4* p = (const float4*)(x + (size_t)bc * HW);
    float4* q = (float4*)(g_xr + (size_t)bc * HW);
    float s = 0.f;
    #pragma unroll
    for (int i = threadIdx.x; i < HW / 4; i += 256) {
        float4 v = p[i];
        s += (v.x + v.y) + (v.z + v.w);
        float4 r;
        r.x = to_tf32(v.x); r.y = to_tf32(v.y); r.z = to_tf32(v.z); r.w = to_tf32(v.w);
        q[i] = r;
    }
    __shared__ float red[8];
    #pragma unroll
    for (int o = 16; o > 0; o >>= 1) s += __shfl_down_sync(0xffffffffu, s, o);
    if ((threadIdx.x & 31) == 0) red[threadIdx.x >> 5] = s;
    __syncthreads();
    if (threadIdx.x < 8) {
        s = red[threadIdx.x];
        #pragma unroll
        for (int o = 4; o > 0; o >>= 1) s += __shfl_down_sync(0xffu, s, o);
        if (threadIdx.x == 0) g_pooled[bc] = s * (1.0f / (float)HW);
    }
}

// fused tf32 rounding of all three weight tensors (float4 granularity)
#define W1_F4 (EE * HID * CC / 4)
#define W2_F4 (EE * HID * HID * 9 / 4)
#define W3_F4 (EE * CC * HID / 4)
__global__ void round_all_kernel(const float* __restrict__ W1, const float* __restrict__ W2,
                                 const float* __restrict__ W3) {
    int i = blockIdx.x * 256 + threadIdx.x;
    const float4* src; float4* dst; int j;
    if (i < W1_F4)                 { src = (const float4*)W1; dst = (float4*)g_w1r; j = i; }
    else if (i < W1_F4 + W2_F4)    { src = (const float4*)W2; dst = (float4*)g_w2r; j = i - W1_F4; }
    else                           { src = (const float4*)W3; dst = (float4*)g_w3r; j = i - W1_F4 - W2_F4; }
    float4 v = src[j];
    float4 r;
    r.x = to_tf32(v.x); r.y = to_tf32(v.y); r.z = to_tf32(v.z); r.w = to_tf32(v.w);
    dst[j] = r;
}

// ============================================================================
// Kernel 2: router MLP + softmax + top-1.  grid = B, 128 threads.
// ============================================================================
__global__ void router_kernel(const float* __restrict__ Wr1, const float* __restrict__ br1,
                              const float* __restrict__ Wr2, const float* __restrict__ br2) {
    int b = blockIdx.x;
    int t = threadIdx.x;
    __shared__ float sp[CC];
    __shared__ float sh[RHD];
    __shared__ float slog[EE];
    sp[t]       = g_pooled[b * CC + t];
    sp[t + 128] = g_pooled[b * CC + t + 128];
    __syncthreads();
    {
        float acc = br1[t];
        const float* w = Wr1 + (size_t)t * CC;
        #pragma unroll 8
        for (int c = 0; c < CC; c++) acc = fmaf(sp[c], w[c], acc);
        sh[t] = fmaxf(acc, 0.f);
    }
    __syncthreads();
    if (t < EE) {
        float l = br2[t];
        const float* w = Wr2 + (size_t)t * RHD;
        #pragma unroll 8
        for (int r = 0; r < RHD; r++) l = fmaf(sh[r], w[r], l);
        slog[t] = l;
    }
    __syncthreads();
    if (t == 0) {
        float l0 = slog[0], l1 = slog[1], l2 = slog[2], l3 = slog[3];
        float m = fmaxf(fmaxf(l0, l1), fmaxf(l2, l3));
        float e0 = __expf(l0 - m), e1 = __expf(l1 - m), e2 = __expf(l2 - m), e3 = __expf(l3 - m);
        float s = e0 + e1 + e2 + e3;
        float p[4] = {e0 / s, e1 / s, e2 / s, e3 / s};
        int idx = 0; float v = p[0];
        #pragma unroll
        for (int i = 1; i < 4; i++) { if (p[i] > v) { v = p[i]; idx = i; } }
        g_expert[b] = idx;
        g_weight[b] = v / (v + 1e-9f);
    }
}

// ============================================================================
// Kernel 3: 1x1 conv C->HID + ReLU. GEMM M=128 N=4096 K=256 (8 chunks).
// 3-stage cp.async pipeline. grid=(32, B), 256 thr, 96KB dyn smem.
// ============================================================================
__global__ __launch_bounds__(256, 2) void gemm1_mma_kernel() {
    extern __shared__ float dsm[];
    const int tid = threadIdx.x, wid = tid >> 5, lane = tid & 31;
    const int warpm = wid >> 1, warpn = wid & 1;
    const int gid = lane >> 2, tig = lane & 3;
    int b  = blockIdx.y;
    int pt = blockIdx.x * 128;
    int e  = g_expert[b];
    const float* A  = g_w1r + (size_t)e * HID * CC;
    const float* Bx = g_xr  + (size_t)b * CC * HW + pt;

    int low = tid & 7, kq = (tid >> 3) & 7, mh0 = tid >> 6;
    int ak0 = kq * 4, amb = mh0 * 8 + low;
    uint32_t wA0 = (((mh0 >> 1) * 4 + (kq >> 1)) * 4 + ((mh0 & 1) | ((kq & 1) << 1))) * 32 + 4 * low;
    int nt_w = lane >> 1;
    uint32_t wBp[4];
    #pragma unroll
    for (int p = 0; p < 4; p++) {
        int kl = p * 8 + wid;
        wBp[p] = ((nt_w * 4 + (kl >> 3)) * 2 + ((kl >> 2) & 1)) * 32
               + (((kl & 3) ^ (nt_w & 3)) * 8) + (lane & 1) * 4;
    }
    uint32_t sm0 = cvta_s(dsm);

    float acc[2][8][4];
    #pragma unroll
    for (int i = 0; i < 2; i++)
        #pragma unroll
        for (int j = 0; j < 8; j++)
            #pragma unroll
            for (int r = 0; r < 4; r++) acc[i][j][r] = 0.f;

    auto load_chunk = [&](int kb, uint32_t base) {
        #pragma unroll
        for (int p = 0; p < 4; p++)
            cp16(base + (wA0 + 1024 * p) * 4, A + (size_t)(amb + 32 * p) * CC + kb + ak0);
        #pragma unroll
        for (int p = 0; p < 4; p++)
            cp16(base + 16384 + wBp[p] * 4, Bx + (size_t)(kb + p * 8 + wid) * HW + lane * 4);
    };

    load_chunk(0, sm0);       cp_commit();
    load_chunk(32, sm0 + 32768); cp_commit();

    int cur = 0, pf = 2;
    for (int it = 0; it < 8; it++) {
        cp_wait_group<1>();
        __syncthreads();
        if (it + 2 < 8) load_chunk((it + 2) * 32, sm0 + pf * 32768);
        cp_commit();     // empty group at the tail keeps wait_group semantics
        const float* sA = dsm + cur * 8192;
        mma_chunk<0>(sA, sA + 4096, warpm, warpn, lane, acc);
        cur = (cur == 2) ? 0 : cur + 1;
        pf  = (pf  == 2) ? 0 : pf  + 1;
    }

    float* Y = g_y1 + (size_t)b * HID * HW;
    #pragma unroll
    for (int mt2 = 0; mt2 < 2; mt2++) {
        int oc0 = warpm * 32 + mt2 * 16 + gid;
        #pragma unroll
        for (int nt2 = 0; nt2 < 8; nt2++) {
            int px = pt + warpn * 64 + nt2 * 8 + 2 * tig;
            float2 v0, v1;
            v0.x = to_tf32(fmaxf(acc[mt2][nt2][0], 0.f));
            v0.y = to_tf32(fmaxf(acc[mt2][nt2][1], 0.f));
            v1.x = to_tf32(fmaxf(acc[mt2][nt2][2], 0.f));
            v1.y = to_tf32(fmaxf(acc[mt2][nt2][3], 0.f));
            *(float2*)(Y + (size_t)oc0 * HW + px)       = v0;
            *(float2*)(Y + (size_t)(oc0 + 8) * HW + px) = v1;
        }
    }
}

// ============================================================================
// Kernel 4: 3x3 conv HID->HID + ReLU, implicit GEMM, K=1152 (36 chunks).
// 3-stage cp.async pipeline. grid=(32, B), 256 thr, 96KB dyn smem.
// ============================================================================
__global__ __launch_bounds__(256, 2) void conv3_mma_kernel() {
    extern __shared__ float dsm[];
    const int tid = threadIdx.x, wid = tid >> 5, lane = tid & 31;
    const int warpm = wid >> 1, warpn = wid & 1;
    const int gid = lane >> 2, tig = lane & 3;
    int b  = blockIdx.y;
    int pb = blockIdx.x;
    int pbase = pb << 7;
    int y0 = pb << 1;
    int e  = g_expert[b];
    const float* A  = g_w2r + (size_t)e * (HID * HID * 9);  // [128][1152]
    const float* Y1 = g_y1 + (size_t)b * HID * HW;

    int low = tid & 7, kq = (tid >> 3) & 7, mh0 = tid >> 6;
    int ak0 = kq * 4, amb = mh0 * 8 + low;
    uint32_t wA0 = (((mh0 >> 1) * 4 + (kq >> 1)) * 4 + ((mh0 & 1) | ((kq & 1) << 1))) * 32 + 4 * low;
    int nqL = lane & 15, kbit = lane >> 4;
    int klp[4], col0p[4], rowp[4], s01p[4];
    uint32_t wB0p[4];
    #pragma unroll
    for (int p = 0; p < 4; p++) {
        int kl = 2 * wid + kbit + 16 * (p & 1);
        int nq = nqL + 16 * (p >> 1);
        int n0 = nq * 4;
        int nt = nq >> 1;
        klp[p]   = kl;
        col0p[p] = n0 & 63;
        rowp[p]  = n0 >> 6;
        s01p[p]  = nt & 3;
        int fl0p = (kl & 3) * 8 + (nq & 1) * 4;
        wB0p[p]  = ((nt * 4 + (kl >> 3)) * 2 + ((kl >> 2) & 1)) * 32
                 + (fl0p ^ ((nt & 4) << 2));
    }
    uint32_t sm0 = cvta_s(dsm);

    float acc[2][8][4];
    #pragma unroll
    for (int i = 0; i < 2; i++)
        #pragma unroll
        for (int j = 0; j < 8; j++)
            #pragma unroll
            for (int r = 0; r < 4; r++) acc[i][j][r] = 0.f;

    auto load_chunk = [&](int kb, uint32_t base) {
        #pragma unroll
        for (int p = 0; p < 4; p++)
            cp16(base + (wA0 + 1024 * p) * 4, A + (size_t)(amb + 32 * p) * 1152 + kb + ak0);
        uint32_t bB = base + 16384;
        #pragma unroll
        for (int p = 0; p < 4; p++) {
            int k   = kb + klp[p];
            int ic  = k / 9;
            int tap = k - ic * 9;
            int ky  = tap / 3;
            int dx  = tap - ky * 3 - 1;
            int gy  = y0 + rowp[p] + ky - 1;
            bool vy = ((unsigned)gy < 64u);
            const float* srow = Y1 + (size_t)ic * HW + (gy << 6);
            #pragma unroll
            for (int j = 0; j < 4; j++) {
                int gx  = col0p[p] + j + dx;
                bool ok = vy & ((unsigned)gx < 64u);
                cp4(bB + (wB0p[p] + (j ^ s01p[p])) * 4, ok ? (srow + gx) : Y1, ok ? 4u : 0u);
            }
        }
    };

    load_chunk(0, sm0);          cp_commit();
    load_chunk(32, sm0 + 32768); cp_commit();

    int cur = 0, pf = 2;
    for (int it = 0; it < 36; it++) {
        cp_wait_group<1>();
        __syncthreads();
        if (it + 2 < 36) load_chunk((it + 2) * 32, sm0 + pf * 32768);
        cp_commit();
        const float* sA = dsm + cur * 8192;
        mma_chunk<1>(sA, sA + 4096, warpm, warpn, lane, acc);
        cur = (cur == 2) ? 0 : cur + 1;
        pf  = (pf  == 2) ? 0 : pf  + 1;
    }

    float* Y2 = g_y2 + (size_t)b * HID * HW;
    #pragma unroll
    for (int mt2 = 0; mt2 < 2; mt2++) {
        int oc0 = warpm * 32 + mt2 * 16 + gid;
        #pragma unroll
        for (int nt2 = 0; nt2 < 8; nt2++) {
            int px = pbase + warpn * 64 + nt2 * 8 + 2 * tig;
            float2 v0, v1;
            v0.x = to_tf32(fmaxf(acc[mt2][nt2][0], 0.f));
            v0.y = to_tf32(fmaxf(acc[mt2][nt2][1], 0.f));
            v1.x = to_tf32(fmaxf(acc[mt2][nt2][2], 0.f));
            v1.y = to_tf32(fmaxf(acc[mt2][nt2][3], 0.f));
            *(float2*)(Y2 + (size_t)oc0 * HW + px)       = v0;
            *(float2*)(Y2 + (size_t)(oc0 + 8) * HW + px) = v1;
        }
    }
}

// ============================================================================
// Kernel 5: 1x1 conv HID->C * wgt + residual. GEMM M=256 N=4096 K=128.
// 3-stage cp.async pipeline. grid=(32, 2, B), 256 thr, 96KB dyn smem.
// ============================================================================
__global__ __launch_bounds__(256, 2) void gemm3_mma_kernel(const float* __restrict__ x,
                                                           float* __restrict__ out) {
    extern __shared__ float dsm[];
    const int tid = threadIdx.x, wid = tid >> 5, lane = tid & 31;
    const int warpm = wid >> 1, warpn = wid & 1;
    const int gid = lane >> 2, tig = lane & 3;
    int b  = blockIdx.z;
    int m0 = blockIdx.y * 128;
    int pt = blockIdx.x * 128;
    int e  = g_expert[b];
    float wgt = g_weight[b];
    const float* A  = g_w3r + (size_t)e * (CC * HID) + (size_t)m0 * HID;
    const float* Bx = g_y2  + (size_t)b * HID * HW + pt;

    int low = tid & 7, kq = (tid >> 3) & 7, mh0 = tid >> 6;
    int ak0 = kq * 4, amb = mh0 * 8 + low;
    uint32_t wA0 = (((mh0 >> 1) * 4 + (kq >> 1)) * 4 + ((mh0 & 1) | ((kq & 1) << 1))) * 32 + 4 * low;
    int nt_w = lane >> 1;
    uint32_t wBp[4];
    #pragma unroll
    for (int p = 0; p < 4; p++) {
        int kl = p * 8 + wid;
        wBp[p] = ((nt_w * 4 + (kl >> 3)) * 2 + ((kl >> 2) & 1)) * 32
               + (((kl & 3) ^ (nt_w & 3)) * 8) + (lane & 1) * 4;
    }
    uint32_t sm0 = cvta_s(dsm);

    float acc[2][8][4];
    #pragma unroll
    for (int i = 0; i < 2; i++)
        #pragma unroll
        for (int j = 0; j < 8; j++)
            #pragma unroll
            for (int r = 0; r < 4; r++) acc[i][j][r] = 0.f;

    auto load_chunk = [&](int kb, uint32_t base) {
        #pragma unroll
        for (int p = 0; p < 4; p++)
            cp16(base + (wA0 + 1024 * p) * 4, A + (size_t)(amb + 32 * p) * HID + kb + ak0);
        #pragma unroll
        for (int p = 0; p < 4; p++)
            cp16(base + 16384 + wBp[p] * 4, Bx + (size_t)(kb + p * 8 + wid) * HW + lane * 4);
    };

    load_chunk(0, sm0);          cp_commit();
    load_chunk(32, sm0 + 32768); cp_commit();

    int cur = 0, pf = 2;
    for (int it = 0; it < 4; it++) {
        cp_wait_group<1>();
        __syncthreads();
        if (it + 2 < 4) load_chunk((it + 2) * 32, sm0 + pf * 32768);
        cp_commit();
        const float* sA = dsm + cur * 8192;
        mma_chunk<0>(sA, sA + 4096, warpm, warpn, lane, acc);
        cur = (cur == 2) ? 0 : cur + 1;
        pf  = (pf  == 2) ? 0 : pf  + 1;
    }

    const float* Xb = x   + (size_t)b * CC * HW;
    float*       O  = out + (size_t)b * CC * HW;
    #pragma unroll
    for (int mt2 = 0; mt2 < 2; mt2++) {
        int m_lo = m0 + warpm * 32 + mt2 * 16 + gid;
        int m_hi = m_lo + 8;
        #pragma unroll
        for (int nt2 = 0; nt2 < 8; nt2++) {
            int px = pt + warpn * 64 + nt2 * 8 + 2 * tig;
            float2 x0 = *(const float2*)(Xb + (size_t)m_lo * HW + px);
            float2 x1 = *(const float2*)(Xb + (size_t)m_hi * HW + px);
            float2 v0, v1;
            v0.x = fmaf(wgt, acc[mt2][nt2][0], x0.x);
            v0.y = fmaf(wgt, acc[mt2][nt2][1], x0.y);
            v1.x = fmaf(wgt, acc[mt2][nt2][2], x1.x);
            v1.y = fmaf(wgt, acc[mt2][nt2][3], x1.y);
            *(float2*)(O + (size_t)m_lo * HW + px) = v0;
            *(float2*)(O + (size_t)m_hi * HW + px) = v1;
        }
    }
}

// ============================================================================
extern "C" void kernel_launch(void* const* d_in, const int* in_sizes, int n_in,
                              void* d_out, int out_size) {
    const float* x   = (const float*)d_in[0];
    const float* Wr1 = (const float*)d_in[1];
    const float* br1 = (const float*)d_in[2];
    const float* Wr2 = (const float*)d_in[3];
    const float* br2 = (const float*)d_in[4];
    const float* W1  = (const float*)d_in[5];
    const float* W2  = (const float*)d_in[6];
    const float* W3  = (const float*)d_in[7];
    float* out = (float*)d_out;

    cudaFuncSetAttribute(gemm1_mma_kernel, cudaFuncAttributeMaxDynamicSharedMemorySize, 98304);
    cudaFuncSetAttribute(conv3_mma_kernel, cudaFuncAttributeMaxDynamicSharedMemorySize, 98304);
    cudaFuncSetAttribute(gemm3_mma_kernel, cudaFuncAttributeMaxDynamicSharedMemorySize, 98304);

    pool_round_kernel<<<BB * CC, 256>>>(x);
    round_all_kernel <<<(W1_F4 + W2_F4 + W3_F4 + 255) / 256, 256>>>(W1, W2, W3);
    router_kernel    <<<BB, 128>>>(Wr1, br1, Wr2, br2);
    gemm1_mma_kernel <<<dim3(32, BB), 256, 98304>>>();
    conv3_mma_kernel <<<dim3(32, BB), 256, 98304>>>();
    gemm3_mma_kernel <<<dim3(32, 2, BB), 256, 98304>>>(x, out);
}

// round 15
// speedup vs baseline: 1.0009x; 1.0009x over previous
#include <cuda_runtime.h>
#include <cstdint>

// Problem constants
#define BB  16
#define CC  256
#define HW  4096
#define EE  4
#define HID 128
#define RHD 128

// ---------------- device-global scratch (allowed; no dynamic alloc) ----------
__device__ __align__(16) float g_pooled[BB * CC];
__device__ int   g_expert[BB];
__device__ float g_weight[BB];
__device__ __align__(16) float g_y1[(size_t)BB * HID * HW];    // tf32-rounded
__device__ __align__(16) float g_y2[(size_t)BB * HID * HW];    // tf32-rounded
__device__ __align__(16) float g_xr[(size_t)BB * CC * HW];     // tf32-rounded x
__device__ __align__(16) float g_w1r[EE * HID * CC];
__device__ __align__(16) float g_w2r[EE * HID * HID * 9];
__device__ __align__(16) float g_w3r[EE * CC * HID];

__device__ __forceinline__ float to_tf32(float x) {
    float r; asm("cvt.rna.tf32.f32 %0, %1;" : "=f"(r) : "f"(x)); return r;
}

// m16n8k8 tf32 mma (arch-agnostic PTX, works on plain sm_103 target)
__device__ __forceinline__ void mma_tf32(float* d,
                                         uint32_t a0, uint32_t a1, uint32_t a2, uint32_t a3,
                                         uint32_t b0, uint32_t b1) {
    asm volatile(
        "mma.sync.aligned.m16n8k8.row.col.f32.tf32.tf32.f32 "
        "{%0,%1,%2,%3}, {%4,%5,%6,%7}, {%8,%9}, {%0,%1,%2,%3};"
        : "+f"(d[0]), "+f"(d[1]), "+f"(d[2]), "+f"(d[3])
        : "r"(a0), "r"(a1), "r"(a2), "r"(a3), "r"(b0), "r"(b1));
}

// ---------------- cp.async helpers ------------------------------------------
__device__ __forceinline__ uint32_t cvta_s(const void* p) {
    return (uint32_t)__cvta_generic_to_shared(p);
}
__device__ __forceinline__ void cp16(uint32_t dst, const void* src) {
    asm volatile("cp.async.cg.shared.global [%0], [%1], 16;" :: "r"(dst), "l"(src));
}
__device__ __forceinline__ void cp4(uint32_t dst, const void* src, uint32_t ssz) {
    asm volatile("cp.async.ca.shared.global [%0], [%1], 4, %2;" :: "r"(dst), "l"(src), "r"(ssz));
}
__device__ __forceinline__ void cp_commit()   { asm volatile("cp.async.commit_group;" ::: "memory"); }
template<int N>
__device__ __forceinline__ void cp_wait_group() {
    asm volatile("cp.async.wait_group %0;" :: "n"(N) : "memory");
}

// ============================================================================
// SMEM layouts per 32-K chunk (4096 floats each = 16 KB):
//  A word((m,k)) = ((mt*4+ks)*4 + rgA)*32 + (m&7)*4 + (k&3)
//  B word((n,k)) = ((nt*4+ks)*2 + rg)*32 + (fl ^ swz(nt)),  fl=(k&3)*8+(n&7)
//      GEMM swz = (nt&3)*8 ;  CONV swz = (nt&3) | ((nt&4)<<2)
// Triple buffer: buffer i at byte offset i*32768; B at +16384 within buffer.
// ============================================================================

template<int CONV>
__device__ __forceinline__ void mma_chunk(const float* sA, const float* sB,
                                          int warpm, int warpn, int lane,
                                          float acc[2][8][4]) {
    const int fl0 = (lane & 3) * 8 + (lane >> 2);
    #pragma unroll
    for (int ks = 0; ks < 4; ks++) {
        uint32_t a[2][4];
        #pragma unroll
        for (int mt2 = 0; mt2 < 2; mt2++) {
            const float* pa = sA + ((warpm * 2 + mt2) * 4 + ks) * 128 + lane;
            a[mt2][0] = __float_as_uint(pa[0]);
            a[mt2][1] = __float_as_uint(pa[32]);
            a[mt2][2] = __float_as_uint(pa[64]);
            a[mt2][3] = __float_as_uint(pa[96]);
        }
        // software-pipelined B fragments (one nt ahead of the MMAs)
        auto ldb = [&](int nt2, uint32_t& b0, uint32_t& b1) {
            int nt  = warpn * 8 + nt2;
            int swz = CONV ? ((nt & 3) | ((nt & 4) << 2)) : ((nt & 3) * 8);
            int fx  = fl0 ^ swz;
            const float* pb = sB + (nt * 4 + ks) * 64;
            b0 = __float_as_uint(pb[fx]);
            b1 = __float_as_uint(pb[32 + fx]);
        };
        uint32_t b0c, b1c, b0n, b1n;
        ldb(0, b0c, b1c);
        #pragma unroll
        for (int nt2 = 0; nt2 < 8; nt2++) {
            if (nt2 < 7) ldb(nt2 + 1, b0n, b1n);
            mma_tf32(acc[0][nt2], a[0][0], a[0][1], a[0][2], a[0][3], b0c, b1c);
            mma_tf32(acc[1][nt2], a[1][0], a[1][1], a[1][2], a[1][3], b0c, b1c);
            b0c = b0n; b1c = b1n;
        }
    }
}

// ============================================================================
// Kernel 1: global average pool + tf32-round x into g_xr. grid=B*C, 256 thr.
// ============================================================================
__global__ void pool_round_kernel(const float* __restrict__ x) {
    int bc = blockIdx.x;
    const float4* p = (const float4*)(x + (size_t)bc * HW);
    float4* q = (float4*)(g_xr + (size_t)bc * HW);
    float s = 0.f;
    #pragma unroll
    for (int i = threadIdx.x; i < HW / 4; i += 256) {
        float4 v = p[i];
        s += (v.x + v.y) + (v.z + v.w);
        float4 r;
        r.x = to_tf32(v.x); r.y = to_tf32(v.y); r.z = to_tf32(v.z); r.w = to_tf32(v.w);
        q[i] = r;
    }
    __shared__ float red[8];
    #pragma unroll
    for (int o = 16; o > 0; o >>= 1) s += __shfl_down_sync(0xffffffffu, s, o);
    if ((threadIdx.x & 31) == 0) red[threadIdx.x >> 5] = s;
    __syncthreads();
    if (threadIdx.x < 8) {
        s = red[threadIdx.x];
        #pragma unroll
        for (int o = 4; o > 0; o >>= 1) s += __shfl_down_sync(0xffu, s, o);
        if (threadIdx.x == 0) g_pooled[bc] = s * (1.0f / (float)HW);
    }
}

// fused tf32 rounding of all three weight tensors (float4 granularity)
#define W1_F4 (EE * HID * CC / 4)
#define W2_F4 (EE * HID * HID * 9 / 4)
#define W3_F4 (EE * CC * HID / 4)
__global__ void round_all_kernel(const float* __restrict__ W1, const float* __restrict__ W2,
                                 const float* __restrict__ W3) {
    int i = blockIdx.x * 256 + threadIdx.x;
    const float4* src; float4* dst; int j;
    if (i < W1_F4)                 { src = (const float4*)W1; dst = (float4*)g_w1r; j = i; }
    else if (i < W1_F4 + W2_F4)    { src = (const float4*)W2; dst = (float4*)g_w2r; j = i - W1_F4; }
    else                           { src = (const float4*)W3; dst = (float4*)g_w3r; j = i - W1_F4 - W2_F4; }
    float4 v = src[j];
    float4 r;
    r.x = to_tf32(v.x); r.y = to_tf32(v.y); r.z = to_tf32(v.z); r.w = to_tf32(v.w);
    dst[j] = r;
}

// ============================================================================
// Kernel 2: router MLP + softmax + top-1.  grid = B, 128 threads.
// ============================================================================
__global__ void router_kernel(const float* __restrict__ Wr1, const float* __restrict__ br1,
                              const float* __restrict__ Wr2, const float* __restrict__ br2) {
    int b = blockIdx.x;
    int t = threadIdx.x;
    __shared__ float sp[CC];
    __shared__ float sh[RHD];
    __shared__ float slog[EE];
    sp[t]       = g_pooled[b * CC + t];
    sp[t + 128] = g_pooled[b * CC + t + 128];
    __syncthreads();
    {
        float acc = br1[t];
        const float* w = Wr1 + (size_t)t * CC;
        #pragma unroll 8
        for (int c = 0; c < CC; c++) acc = fmaf(sp[c], w[c], acc);
        sh[t] = fmaxf(acc, 0.f);
    }
    __syncthreads();
    if (t < EE) {
        float l = br2[t];
        const float* w = Wr2 + (size_t)t * RHD;
        #pragma unroll 8
        for (int r = 0; r < RHD; r++) l = fmaf(sh[r], w[r], l);
        slog[t] = l;
    }
    __syncthreads();
    if (t == 0) {
        float l0 = slog[0], l1 = slog[1], l2 = slog[2], l3 = slog[3];
        float m = fmaxf(fmaxf(l0, l1), fmaxf(l2, l3));
        float e0 = __expf(l0 - m), e1 = __expf(l1 - m), e2 = __expf(l2 - m), e3 = __expf(l3 - m);
        float s = e0 + e1 + e2 + e3;
        float p[4] = {e0 / s, e1 / s, e2 / s, e3 / s};
        int idx = 0; float v = p[0];
        #pragma unroll
        for (int i = 1; i < 4; i++) { if (p[i] > v) { v = p[i]; idx = i; } }
        g_expert[b] = idx;
        g_weight[b] = v / (v + 1e-9f);
    }
}

// ============================================================================
// Kernel 3: 1x1 conv C->HID + ReLU. GEMM M=128 N=4096 K=256 (8 chunks).
// 3-stage cp.async pipeline. grid=(32, B), 256 thr, 96KB dyn smem.
// ============================================================================
__global__ __launch_bounds__(256, 2) void gemm1_mma_kernel() {
    extern __shared__ float dsm[];
    const int tid = threadIdx.x, wid = tid >> 5, lane = tid & 31;
    const int warpm = wid >> 1, warpn = wid & 1;
    const int gid = lane >> 2, tig = lane & 3;
    int b  = blockIdx.y;
    int pt = blockIdx.x * 128;
    int e  = g_expert[b];
    const float* A  = g_w1r + (size_t)e * HID * CC;
    const float* Bx = g_xr  + (size_t)b * CC * HW + pt;

    int low = tid & 7, kq = (tid >> 3) & 7, mh0 = tid >> 6;
    int ak0 = kq * 4, amb = mh0 * 8 + low;
    uint32_t wA0 = (((mh0 >> 1) * 4 + (kq >> 1)) * 4 + ((mh0 & 1) | ((kq & 1) << 1))) * 32 + 4 * low;
    int nt_w = lane >> 1;
    uint32_t wBp[4];
    #pragma unroll
    for (int p = 0; p < 4; p++) {
        int kl = p * 8 + wid;
        wBp[p] = ((nt_w * 4 + (kl >> 3)) * 2 + ((kl >> 2) & 1)) * 32
               + (((kl & 3) ^ (nt_w & 3)) * 8) + (lane & 1) * 4;
    }
    uint32_t sm0 = cvta_s(dsm);

    float acc[2][8][4];
    #pragma unroll
    for (int i = 0; i < 2; i++)
        #pragma unroll
        for (int j = 0; j < 8; j++)
            #pragma unroll
            for (int r = 0; r < 4; r++) acc[i][j][r] = 0.f;

    auto load_chunk = [&](int kb, uint32_t base) {
        #pragma unroll
        for (int p = 0; p < 4; p++)
            cp16(base + (wA0 + 1024 * p) * 4, A + (size_t)(amb + 32 * p) * CC + kb + ak0);
        #pragma unroll
        for (int p = 0; p < 4; p++)
            cp16(base + 16384 + wBp[p] * 4, Bx + (size_t)(kb + p * 8 + wid) * HW + lane * 4);
    };

    load_chunk(0, sm0);       cp_commit();
    load_chunk(32, sm0 + 32768); cp_commit();

    int cur = 0, pf = 2;
    for (int it = 0; it < 8; it++) {
        cp_wait_group<1>();
        __syncthreads();
        if (it + 2 < 8) load_chunk((it + 2) * 32, sm0 + pf * 32768);
        cp_commit();     // empty group at the tail keeps wait_group semantics
        const float* sA = dsm + cur * 8192;
        mma_chunk<0>(sA, sA + 4096, warpm, warpn, lane, acc);
        cur = (cur == 2) ? 0 : cur + 1;
        pf  = (pf  == 2) ? 0 : pf  + 1;
    }

    float* Y = g_y1 + (size_t)b * HID * HW;
    #pragma unroll
    for (int mt2 = 0; mt2 < 2; mt2++) {
        int oc0 = warpm * 32 + mt2 * 16 + gid;
        #pragma unroll
        for (int nt2 = 0; nt2 < 8; nt2++) {
            int px = pt + warpn * 64 + nt2 * 8 + 2 * tig;
            float2 v0, v1;
            v0.x = to_tf32(fmaxf(acc[mt2][nt2][0], 0.f));
            v0.y = to_tf32(fmaxf(acc[mt2][nt2][1], 0.f));
            v1.x = to_tf32(fmaxf(acc[mt2][nt2][2], 0.f));
            v1.y = to_tf32(fmaxf(acc[mt2][nt2][3], 0.f));
            *(float2*)(Y + (size_t)oc0 * HW + px)       = v0;
            *(float2*)(Y + (size_t)(oc0 + 8) * HW + px) = v1;
        }
    }
}

// ============================================================================
// Kernel 4: 3x3 conv HID->HID + ReLU, implicit GEMM, K=1152 (36 chunks).
// 3-stage cp.async pipeline. grid=(32, B), 256 thr, 96KB dyn smem.
// ============================================================================
__global__ __launch_bounds__(256, 2) void conv3_mma_kernel() {
    extern __shared__ float dsm[];
    const int tid = threadIdx.x, wid = tid >> 5, lane = tid & 31;
    const int warpm = wid >> 1, warpn = wid & 1;
    const int gid = lane >> 2, tig = lane & 3;
    int b  = blockIdx.y;
    int pb = blockIdx.x;
    int pbase = pb << 7;
    int y0 = pb << 1;
    int e  = g_expert[b];
    const float* A  = g_w2r + (size_t)e * (HID * HID * 9);  // [128][1152]
    const float* Y1 = g_y1 + (size_t)b * HID * HW;

    int low = tid & 7, kq = (tid >> 3) & 7, mh0 = tid >> 6;
    int ak0 = kq * 4, amb = mh0 * 8 + low;
    uint32_t wA0 = (((mh0 >> 1) * 4 + (kq >> 1)) * 4 + ((mh0 & 1) | ((kq & 1) << 1))) * 32 + 4 * low;
    int nqL = lane & 15, kbit = lane >> 4;
    int klp[4], col0p[4], rowp[4], s01p[4];
    uint32_t wB0p[4];
    #pragma unroll
    for (int p = 0; p < 4; p++) {
        int kl = 2 * wid + kbit + 16 * (p & 1);
        int nq = nqL + 16 * (p >> 1);
        int n0 = nq * 4;
        int nt = nq >> 1;
        klp[p]   = kl;
        col0p[p] = n0 & 63;
        rowp[p]  = n0 >> 6;
        s01p[p]  = nt & 3;
        int fl0p = (kl & 3) * 8 + (nq & 1) * 4;
        wB0p[p]  = ((nt * 4 + (kl >> 3)) * 2 + ((kl >> 2) & 1)) * 32
                 + (fl0p ^ ((nt & 4) << 2));
    }
    uint32_t sm0 = cvta_s(dsm);

    float acc[2][8][4];
    #pragma unroll
    for (int i = 0; i < 2; i++)
        #pragma unroll
        for (int j = 0; j < 8; j++)
            #pragma unroll
            for (int r = 0; r < 4; r++) acc[i][j][r] = 0.f;

    auto load_chunk = [&](int kb, uint32_t base) {
        #pragma unroll
        for (int p = 0; p < 4; p++)
            cp16(base + (wA0 + 1024 * p) * 4, A + (size_t)(amb + 32 * p) * 1152 + kb + ak0);
        uint32_t bB = base + 16384;
        #pragma unroll
        for (int p = 0; p < 4; p++) {
            int k   = kb + klp[p];
            int ic  = k / 9;
            int tap = k - ic * 9;
            int ky  = tap / 3;
            int dx  = tap - ky * 3 - 1;
            int gy  = y0 + rowp[p] + ky - 1;
            bool vy = ((unsigned)gy < 64u);
            const float* srow = Y1 + (size_t)ic * HW + (gy << 6);
            #pragma unroll
            for (int j = 0; j < 4; j++) {
                int gx  = col0p[p] + j + dx;
                bool ok = vy & ((unsigned)gx < 64u);
                cp4(bB + (wB0p[p] + (j ^ s01p[p])) * 4, ok ? (srow + gx) : Y1, ok ? 4u : 0u);
            }
        }
    };

    load_chunk(0, sm0);          cp_commit();
    load_chunk(32, sm0 + 32768); cp_commit();

    int cur = 0, pf = 2;
    for (int it = 0; it < 36; it++) {
        cp_wait_group<1>();
        __syncthreads();
        if (it + 2 < 36) load_chunk((it + 2) * 32, sm0 + pf * 32768);
        cp_commit();
        const float* sA = dsm + cur * 8192;
        mma_chunk<1>(sA, sA + 4096, warpm, warpn, lane, acc);
        cur = (cur == 2) ? 0 : cur + 1;
        pf  = (pf  == 2) ? 0 : pf  + 1;
    }

    float* Y2 = g_y2 + (size_t)b * HID * HW;
    #pragma unroll
    for (int mt2 = 0; mt2 < 2; mt2++) {
        int oc0 = warpm * 32 + mt2 * 16 + gid;
        #pragma unroll
        for (int nt2 = 0; nt2 < 8; nt2++) {
            int px = pbase + warpn * 64 + nt2 * 8 + 2 * tig;
            float2 v0, v1;
            v0.x = to_tf32(fmaxf(acc[mt2][nt2][0], 0.f));
            v0.y = to_tf32(fmaxf(acc[mt2][nt2][1], 0.f));
            v1.x = to_tf32(fmaxf(acc[mt2][nt2][2], 0.f));
            v1.y = to_tf32(fmaxf(acc[mt2][nt2][3], 0.f));
            *(float2*)(Y2 + (size_t)oc0 * HW + px)       = v0;
            *(float2*)(Y2 + (size_t)(oc0 + 8) * HW + px) = v1;
        }
    }
}

// ============================================================================
// Kernel 5: 1x1 conv HID->C * wgt + residual. GEMM M=256 N=4096 K=128.
// 3-stage cp.async pipeline. grid=(32, 2, B), 256 thr, 96KB dyn smem.
// ============================================================================
__global__ __launch_bounds__(256, 2) void gemm3_mma_kernel(const float* __restrict__ x,
                                                           float* __restrict__ out) {
    extern __shared__ float dsm[];
    const int tid = threadIdx.x, wid = tid >> 5, lane = tid & 31;
    const int warpm = wid >> 1, warpn = wid & 1;
    const int gid = lane >> 2, tig = lane & 3;
    int b  = blockIdx.z;
    int m0 = blockIdx.y * 128;
    int pt = blockIdx.x * 128;
    int e  = g_expert[b];
    float wgt = g_weight[b];
    const float* A  = g_w3r + (size_t)e * (CC * HID) + (size_t)m0 * HID;
    const float* Bx = g_y2  + (size_t)b * HID * HW + pt;

    int low = tid & 7, kq = (tid >> 3) & 7, mh0 = tid >> 6;
    int ak0 = kq * 4, amb = mh0 * 8 + low;
    uint32_t wA0 = (((mh0 >> 1) * 4 + (kq >> 1)) * 4 + ((mh0 & 1) | ((kq & 1) << 1))) * 32 + 4 * low;
    int nt_w = lane >> 1;
    uint32_t wBp[4];
    #pragma unroll
    for (int p = 0; p < 4; p++) {
        int kl = p * 8 + wid;
        wBp[p] = ((nt_w * 4 + (kl >> 3)) * 2 + ((kl >> 2) & 1)) * 32
               + (((kl & 3) ^ (nt_w & 3)) * 8) + (lane & 1) * 4;
    }
    uint32_t sm0 = cvta_s(dsm);

    float acc[2][8][4];
    #pragma unroll
    for (int i = 0; i < 2; i++)
        #pragma unroll
        for (int j = 0; j < 8; j++)
            #pragma unroll
            for (int r = 0; r < 4; r++) acc[i][j][r] = 0.f;

    auto load_chunk = [&](int kb, uint32_t base) {
        #pragma unroll
        for (int p = 0; p < 4; p++)
            cp16(base + (wA0 + 1024 * p) * 4, A + (size_t)(amb + 32 * p) * HID + kb + ak0);
        #pragma unroll
        for (int p = 0; p < 4; p++)
            cp16(base + 16384 + wBp[p] * 4, Bx + (size_t)(kb + p * 8 + wid) * HW + lane * 4);
    };

    load_chunk(0, sm0);          cp_commit();
    load_chunk(32, sm0 + 32768); cp_commit();

    int cur = 0, pf = 2;
    for (int it = 0; it < 4; it++) {
        cp_wait_group<1>();
        __syncthreads();
        if (it + 2 < 4) load_chunk((it + 2) * 32, sm0 + pf * 32768);
        cp_commit();
        const float* sA = dsm + cur * 8192;
        mma_chunk<0>(sA, sA + 4096, warpm, warpn, lane, acc);
        cur = (cur == 2) ? 0 : cur + 1;
        pf  = (pf  == 2) ? 0 : pf  + 1;
    }

    const float* Xb = x   + (size_t)b * CC * HW;
    float*       O  = out + (size_t)b * CC * HW;
    #pragma unroll
    for (int mt2 = 0; mt2 < 2; mt2++) {
        int m_lo = m0 + warpm * 32 + mt2 * 16 + gid;
        int m_hi = m_lo + 8;
        #pragma unroll
        for (int nt2 = 0; nt2 < 8; nt2++) {
            int px = pt + warpn * 64 + nt2 * 8 + 2 * tig;
            float2 x0 = *(const float2*)(Xb + (size_t)m_lo * HW + px);
            float2 x1 = *(const float2*)(Xb + (size_t)m_hi * HW + px);
            float2 v0, v1;
            v0.x = fmaf(wgt, acc[mt2][nt2][0], x0.x);
            v0.y = fmaf(wgt, acc[mt2][nt2][1], x0.y);
            v1.x = fmaf(wgt, acc[mt2][nt2][2], x1.x);
            v1.y = fmaf(wgt, acc[mt2][nt2][3], x1.y);
            *(float2*)(O + (size_t)m_lo * HW + px) = v0;
            *(float2*)(O + (size_t)m_hi * HW + px) = v1;
        }
    }
}

// ============================================================================
extern "C" void kernel_launch(void* const* d_in, const int* in_sizes, int n_in,
                              void* d_out, int out_size) {
    const float* x   = (const float*)d_in[0];
    const float* Wr1 = (const float*)d_in[1];
    const float* br1 = (const float*)d_in[2];
    const float* Wr2 = (const float*)d_in[3];
    const float* br2 = (const float*)d_in[4];
    const float* W1  = (const float*)d_in[5];
    const float* W2  = (const float*)d_in[6];
    const float* W3  = (const float*)d_in[7];
    float* out = (float*)d_out;

    cudaFuncSetAttribute(gemm1_mma_kernel, cudaFuncAttributeMaxDynamicSharedMemorySize, 98304);
    cudaFuncSetAttribute(conv3_mma_kernel, cudaFuncAttributeMaxDynamicSharedMemorySize, 98304);
    cudaFuncSetAttribute(gemm3_mma_kernel, cudaFuncAttributeMaxDynamicSharedMemorySize, 98304);

    pool_round_kernel<<<BB * CC, 256>>>(x);
    round_all_kernel <<<(W1_F4 + W2_F4 + W3_F4 + 255) / 256, 256>>>(W1, W2, W3);
    router_kernel    <<<BB, 128>>>(Wr1, br1, Wr2, br2);
    gemm1_mma_kernel <<<dim3(32, BB), 256, 98304>>>();
    conv3_mma_kernel <<<dim3(32, BB), 256, 98304>>>();
    gemm3_mma_kernel <<<dim3(32, 2, BB), 256, 98304>>>(x, out);
}

// round 16
// speedup vs baseline: 1.0012x; 1.0004x over previous
#include <cuda_runtime.h>
#include <cstdint>

// Problem constants
#define BB  16
#define CC  256
#define HW  4096
#define EE  4
#define HID 128
#define RHD 128

// ---------------- device-global scratch (allowed; no dynamic alloc) ----------
__device__ __align__(16) float g_pooled[BB * CC];
__device__ int   g_expert[BB];
__device__ float g_weight[BB];
__device__ __align__(16) float g_y1[(size_t)BB * HID * HW];    // tf32-rounded
__device__ __align__(16) float g_y2[(size_t)BB * HID * HW];    // tf32-rounded
__device__ __align__(16) float g_xr[(size_t)BB * CC * HW];     // tf32-rounded x
__device__ __align__(16) float g_w1r[EE * HID * CC];
__device__ __align__(16) float g_w2r[EE * HID * HID * 9];
__device__ __align__(16) float g_w3r[EE * CC * HID];

__device__ __forceinline__ float to_tf32(float x) {
    float r; asm("cvt.rna.tf32.f32 %0, %1;" : "=f"(r) : "f"(x)); return r;
}

// m16n8k8 tf32 mma (arch-agnostic PTX, works on plain sm_103 target)
__device__ __forceinline__ void mma_tf32(float* d,
                                         uint32_t a0, uint32_t a1, uint32_t a2, uint32_t a3,
                                         uint32_t b0, uint32_t b1) {
    asm volatile(
        "mma.sync.aligned.m16n8k8.row.col.f32.tf32.tf32.f32 "
        "{%0,%1,%2,%3}, {%4,%5,%6,%7}, {%8,%9}, {%0,%1,%2,%3};"
        : "+f"(d[0]), "+f"(d[1]), "+f"(d[2]), "+f"(d[3])
        : "r"(a0), "r"(a1), "r"(a2), "r"(a3), "r"(b0), "r"(b1));
}

// ---------------- cp.async helpers ------------------------------------------
__device__ __forceinline__ uint32_t cvta_s(const void* p) {
    return (uint32_t)__cvta_generic_to_shared(p);
}
__device__ __forceinline__ void cp16(uint32_t dst, const void* src) {
    asm volatile("cp.async.cg.shared.global [%0], [%1], 16;" :: "r"(dst), "l"(src));
}
__device__ __forceinline__ void cp4(uint32_t dst, const void* src, uint32_t ssz) {
    asm volatile("cp.async.ca.shared.global [%0], [%1], 4, %2;" :: "r"(dst), "l"(src), "r"(ssz));
}
__device__ __forceinline__ void cp_commit()   { asm volatile("cp.async.commit_group;" ::: "memory"); }
template<int N>
__device__ __forceinline__ void cp_wait_group() {
    asm volatile("cp.async.wait_group %0;" :: "n"(N) : "memory");
}

// ============================================================================
// SMEM layouts per 32-K chunk (4096 floats each = 16 KB):
//  A word((m,k)) = ((mt*4+ks)*4 + rgA)*32 + (m&7)*4 + (k&3)
//  B word((n,k)) = ((nt*4+ks)*2 + rg)*32 + (fl ^ swz(nt)),  fl=(k&3)*8+(n&7)
//      GEMM swz = (nt&3)*8 ;  CONV swz = (nt&3) | ((nt&4)<<2)
// Triple buffer: buffer i at byte offset i*32768; B at +16384 within buffer.
// ============================================================================

template<int CONV>
__device__ __forceinline__ void mma_chunk(const float* sA, const float* sB,
                                          int warpm, int warpn, int lane,
                                          float acc[2][8][4]) {
    const int fl0 = (lane & 3) * 8 + (lane >> 2);
    #pragma unroll
    for (int ks = 0; ks < 4; ks++) {
        uint32_t a[2][4];
        #pragma unroll
        for (int mt2 = 0; mt2 < 2; mt2++) {
            const float* pa = sA + ((warpm * 2 + mt2) * 4 + ks) * 128 + lane;
            a[mt2][0] = __float_as_uint(pa[0]);
            a[mt2][1] = __float_as_uint(pa[32]);
            a[mt2][2] = __float_as_uint(pa[64]);
            a[mt2][3] = __float_as_uint(pa[96]);
        }
        // software-pipelined B fragments (one nt ahead of the MMAs)
        auto ldb = [&](int nt2, uint32_t& b0, uint32_t& b1) {
            int nt  = warpn * 8 + nt2;
            int swz = CONV ? ((nt & 3) | ((nt & 4) << 2)) : ((nt & 3) * 8);
            int fx  = fl0 ^ swz;
            const float* pb = sB + (nt * 4 + ks) * 64;
            b0 = __float_as_uint(pb[fx]);
            b1 = __float_as_uint(pb[32 + fx]);
        };
        uint32_t b0c, b1c, b0n, b1n;
        ldb(0, b0c, b1c);
        #pragma unroll
        for (int nt2 = 0; nt2 < 8; nt2++) {
            if (nt2 < 7) ldb(nt2 + 1, b0n, b1n);
            mma_tf32(acc[0][nt2], a[0][0], a[0][1], a[0][2], a[0][3], b0c, b1c);
            mma_tf32(acc[1][nt2], a[1][0], a[1][1], a[1][2], a[1][3], b0c, b1c);
            b0c = b0n; b1c = b1n;
        }
    }
}

// ============================================================================
// Kernel 1: global average pool + tf32-round x into g_xr. grid=B*C, 256 thr.
// ============================================================================
__global__ void pool_round_kernel(const float* __restrict__ x) {
    int bc = blockIdx.x;
    const float4* p = (const float4*)(x + (size_t)bc * HW);
    float4* q = (float4*)(g_xr + (size_t)bc * HW);
    float s = 0.f;
    #pragma unroll
    for (int i = threadIdx.x; i < HW / 4; i += 256) {
        float4 v = p[i];
        s += (v.x + v.y) + (v.z + v.w);
        float4 r;
        r.x = to_tf32(v.x); r.y = to_tf32(v.y); r.z = to_tf32(v.z); r.w = to_tf32(v.w);
        q[i] = r;
    }
    __shared__ float red[8];
    #pragma unroll
    for (int o = 16; o > 0; o >>= 1) s += __shfl_down_sync(0xffffffffu, s, o);
    if ((threadIdx.x & 31) == 0) red[threadIdx.x >> 5] = s;
    __syncthreads();
    if (threadIdx.x < 8) {
        s = red[threadIdx.x];
        #pragma unroll
        for (int o = 4; o > 0; o >>= 1) s += __shfl_down_sync(0xffu, s, o);
        if (threadIdx.x == 0) g_pooled[bc] = s * (1.0f / (float)HW);
    }
}

// fused tf32 rounding of all three weight tensors (float4 granularity)
#define W1_F4 (EE * HID * CC / 4)
#define W2_F4 (EE * HID * HID * 9 / 4)
#define W3_F4 (EE * CC * HID / 4)
__global__ void round_all_kernel(const float* __restrict__ W1, const float* __restrict__ W2,
                                 const float* __restrict__ W3) {
    int i = blockIdx.x * 256 + threadIdx.x;
    const float4* src; float4* dst; int j;
    if (i < W1_F4)                 { src = (const float4*)W1; dst = (float4*)g_w1r; j = i; }
    else if (i < W1_F4 + W2_F4)    { src = (const float4*)W2; dst = (float4*)g_w2r; j = i - W1_F4; }
    else                           { src = (const float4*)W3; dst = (float4*)g_w3r; j = i - W1_F4 - W2_F4; }
    float4 v = src[j];
    float4 r;
    r.x = to_tf32(v.x); r.y = to_tf32(v.y); r.z = to_tf32(v.z); r.w = to_tf32(v.w);
    dst[j] = r;
}

// ============================================================================
// Kernel 2: router MLP + softmax + top-1.  grid = B, 128 threads.
// ============================================================================
__global__ void router_kernel(const float* __restrict__ Wr1, const float* __restrict__ br1,
                              const float* __restrict__ Wr2, const float* __restrict__ br2) {
    int b = blockIdx.x;
    int t = threadIdx.x;
    __shared__ float sp[CC];
    __shared__ float sh[RHD];
    __shared__ float slog[EE];
    sp[t]       = g_pooled[b * CC + t];
    sp[t + 128] = g_pooled[b * CC + t + 128];
    __syncthreads();
    {
        float acc = br1[t];
        const float* w = Wr1 + (size_t)t * CC;
        #pragma unroll 8
        for (int c = 0; c < CC; c++) acc = fmaf(sp[c], w[c], acc);
        sh[t] = fmaxf(acc, 0.f);
    }
    __syncthreads();
    if (t < EE) {
        float l = br2[t];
        const float* w = Wr2 + (size_t)t * RHD;
        #pragma unroll 8
        for (int r = 0; r < RHD; r++) l = fmaf(sh[r], w[r], l);
        slog[t] = l;
    }
    __syncthreads();
    if (t == 0) {
        float l0 = slog[0], l1 = slog[1], l2 = slog[2], l3 = slog[3];
        float m = fmaxf(fmaxf(l0, l1), fmaxf(l2, l3));
        float e0 = __expf(l0 - m), e1 = __expf(l1 - m), e2 = __expf(l2 - m), e3 = __expf(l3 - m);
        float s = e0 + e1 + e2 + e3;
        float p[4] = {e0 / s, e1 / s, e2 / s, e3 / s};
        int idx = 0; float v = p[0];
        #pragma unroll
        for (int i = 1; i < 4; i++) { if (p[i] > v) { v = p[i]; idx = i; } }
        g_expert[b] = idx;
        g_weight[b] = v / (v + 1e-9f);
    }
}

// ============================================================================
// Kernel 3: 1x1 conv C->HID + ReLU. GEMM M=128 N=4096 K=256 (8 chunks).
// 3-stage cp.async pipeline. grid=(32, B), 256 thr, 96KB dyn smem.
// ============================================================================
__global__ __launch_bounds__(256, 2) void gemm1_mma_kernel() {
    extern __shared__ float dsm[];
    const int tid = threadIdx.x, wid = tid >> 5, lane = tid & 31;
    const int warpm = wid >> 1, warpn = wid & 1;
    const int gid = lane >> 2, tig = lane & 3;
    int b  = blockIdx.y;
    int pt = blockIdx.x * 128;
    int e  = g_expert[b];
    const float* A  = g_w1r + (size_t)e * HID * CC;
    const float* Bx = g_xr  + (size_t)b * CC * HW + pt;

    int low = tid & 7, kq = (tid >> 3) & 7, mh0 = tid >> 6;
    int ak0 = kq * 4, amb = mh0 * 8 + low;
    uint32_t wA0 = (((mh0 >> 1) * 4 + (kq >> 1)) * 4 + ((mh0 & 1) | ((kq & 1) << 1))) * 32 + 4 * low;
    int nt_w = lane >> 1;
    uint32_t wBp[4];
    #pragma unroll
    for (int p = 0; p < 4; p++) {
        int kl = p * 8 + wid;
        wBp[p] = ((nt_w * 4 + (kl >> 3)) * 2 + ((kl >> 2) & 1)) * 32
               + (((kl & 3) ^ (nt_w & 3)) * 8) + (lane & 1) * 4;
    }
    uint32_t sm0 = cvta_s(dsm);

    float acc[2][8][4];
    #pragma unroll
    for (int i = 0; i < 2; i++)
        #pragma unroll
        for (int j = 0; j < 8; j++)
            #pragma unroll
            for (int r = 0; r < 4; r++) acc[i][j][r] = 0.f;

    auto load_chunk = [&](int kb, uint32_t base) {
        #pragma unroll
        for (int p = 0; p < 4; p++)
            cp16(base + (wA0 + 1024 * p) * 4, A + (size_t)(amb + 32 * p) * CC + kb + ak0);
        #pragma unroll
        for (int p = 0; p < 4; p++)
            cp16(base + 16384 + wBp[p] * 4, Bx + (size_t)(kb + p * 8 + wid) * HW + lane * 4);
    };

    load_chunk(0, sm0);       cp_commit();
    load_chunk(32, sm0 + 32768); cp_commit();

    int cur = 0, pf = 2;
    for (int it = 0; it < 8; it++) {
        cp_wait_group<1>();
        __syncthreads();
        if (it + 2 < 8) load_chunk((it + 2) * 32, sm0 + pf * 32768);
        cp_commit();     // empty group at the tail keeps wait_group semantics
        const float* sA = dsm + cur * 8192;
        mma_chunk<0>(sA, sA + 4096, warpm, warpn, lane, acc);
        cur = (cur == 2) ? 0 : cur + 1;
        pf  = (pf  == 2) ? 0 : pf  + 1;
    }

    float* Y = g_y1 + (size_t)b * HID * HW;
    #pragma unroll
    for (int mt2 = 0; mt2 < 2; mt2++) {
        int oc0 = warpm * 32 + mt2 * 16 + gid;
        #pragma unroll
        for (int nt2 = 0; nt2 < 8; nt2++) {
            int px = pt + warpn * 64 + nt2 * 8 + 2 * tig;
            float2 v0, v1;
            v0.x = to_tf32(fmaxf(acc[mt2][nt2][0], 0.f));
            v0.y = to_tf32(fmaxf(acc[mt2][nt2][1], 0.f));
            v1.x = to_tf32(fmaxf(acc[mt2][nt2][2], 0.f));
            v1.y = to_tf32(fmaxf(acc[mt2][nt2][3], 0.f));
            *(float2*)(Y + (size_t)oc0 * HW + px)       = v0;
            *(float2*)(Y + (size_t)(oc0 + 8) * HW + px) = v1;
        }
    }
}

// ============================================================================
// Kernel 4: 3x3 conv HID->HID + ReLU, implicit GEMM, K=1152 (36 chunks).
// 3-stage cp.async pipeline. grid=(32, B), 256 thr, 96KB dyn smem.
// ============================================================================
__global__ __launch_bounds__(256, 2) void conv3_mma_kernel() {
    extern __shared__ float dsm[];
    const int tid = threadIdx.x, wid = tid >> 5, lane = tid & 31;
    const int warpm = wid >> 1, warpn = wid & 1;
    const int gid = lane >> 2, tig = lane & 3;
    int b  = blockIdx.y;
    int pb = blockIdx.x;
    int pbase = pb << 7;
    int y0 = pb << 1;
    int e  = g_expert[b];
    const float* A  = g_w2r + (size_t)e * (HID * HID * 9);  // [128][1152]
    const float* Y1 = g_y1 + (size_t)b * HID * HW;

    int low = tid & 7, kq = (tid >> 3) & 7, mh0 = tid >> 6;
    int ak0 = kq * 4, amb = mh0 * 8 + low;
    uint32_t wA0 = (((mh0 >> 1) * 4 + (kq >> 1)) * 4 + ((mh0 & 1) | ((kq & 1) << 1))) * 32 + 4 * low;
    int nqL = lane & 15, kbit = lane >> 4;
    int klp[4], col0p[4], rowp[4], s01p[4];
    uint32_t wB0p[4];
    #pragma unroll
    for (int p = 0; p < 4; p++) {
        int kl = 2 * wid + kbit + 16 * (p & 1);
        int nq = nqL + 16 * (p >> 1);
        int n0 = nq * 4;
        int nt = nq >> 1;
        klp[p]   = kl;
        col0p[p] = n0 & 63;
        rowp[p]  = n0 >> 6;
        s01p[p]  = nt & 3;
        int fl0p = (kl & 3) * 8 + (nq & 1) * 4;
        wB0p[p]  = ((nt * 4 + (kl >> 3)) * 2 + ((kl >> 2) & 1)) * 32
                 + (fl0p ^ ((nt & 4) << 2));
    }
    uint32_t sm0 = cvta_s(dsm);

    float acc[2][8][4];
    #pragma unroll
    for (int i = 0; i < 2; i++)
        #pragma unroll
        for (int j = 0; j < 8; j++)
            #pragma unroll
            for (int r = 0; r < 4; r++) acc[i][j][r] = 0.f;

    auto load_chunk = [&](int kb, uint32_t base) {
        #pragma unroll
        for (int p = 0; p < 4; p++)
            cp16(base + (wA0 + 1024 * p) * 4, A + (size_t)(amb + 32 * p) * 1152 + kb + ak0);
        uint32_t bB = base + 16384;
        #pragma unroll
        for (int p = 0; p < 4; p++) {
            int k   = kb + klp[p];
            int ic  = k / 9;
            int tap = k - ic * 9;
            int ky  = tap / 3;
            int dx  = tap - ky * 3 - 1;
            int gy  = y0 + rowp[p] + ky - 1;
            bool vy = ((unsigned)gy < 64u);
            const float* srow = Y1 + (size_t)ic * HW + (gy << 6);
            #pragma unroll
            for (int j = 0; j < 4; j++) {
                int gx  = col0p[p] + j + dx;
                bool ok = vy & ((unsigned)gx < 64u);
                cp4(bB + (wB0p[p] + (j ^ s01p[p])) * 4, ok ? (srow + gx) : Y1, ok ? 4u : 0u);
            }
        }
    };

    load_chunk(0, sm0);          cp_commit();
    load_chunk(32, sm0 + 32768); cp_commit();

    int cur = 0, pf = 2;
    for (int it = 0; it < 36; it++) {
        cp_wait_group<1>();
        __syncthreads();
        if (it + 2 < 36) load_chunk((it + 2) * 32, sm0 + pf * 32768);
        cp_commit();
        const float* sA = dsm + cur * 8192;
        mma_chunk<1>(sA, sA + 4096, warpm, warpn, lane, acc);
        cur = (cur == 2) ? 0 : cur + 1;
        pf  = (pf  == 2) ? 0 : pf  + 1;
    }

    float* Y2 = g_y2 + (size_t)b * HID * HW;
    #pragma unroll
    for (int mt2 = 0; mt2 < 2; mt2++) {
        int oc0 = warpm * 32 + mt2 * 16 + gid;
        #pragma unroll
        for (int nt2 = 0; nt2 < 8; nt2++) {
            int px = pbase + warpn * 64 + nt2 * 8 + 2 * tig;
            float2 v0, v1;
            v0.x = to_tf32(fmaxf(acc[mt2][nt2][0], 0.f));
            v0.y = to_tf32(fmaxf(acc[mt2][nt2][1], 0.f));
            v1.x = to_tf32(fmaxf(acc[mt2][nt2][2], 0.f));
            v1.y = to_tf32(fmaxf(acc[mt2][nt2][3], 0.f));
            *(float2*)(Y2 + (size_t)oc0 * HW + px)       = v0;
            *(float2*)(Y2 + (size_t)(oc0 + 8) * HW + px) = v1;
        }
    }
}

// ============================================================================
// Kernel 5: 1x1 conv HID->C * wgt + residual. GEMM M=256 N=4096 K=128.
// 3-stage cp.async pipeline. grid=(32, 2, B), 256 thr, 96KB dyn smem.
// ============================================================================
__global__ __launch_bounds__(256, 2) void gemm3_mma_kernel(const float* __restrict__ x,
                                                           float* __restrict__ out) {
    extern __shared__ float dsm[];
    const int tid = threadIdx.x, wid = tid >> 5, lane = tid & 31;
    const int warpm = wid >> 1, warpn = wid & 1;
    const int gid = lane >> 2, tig = lane & 3;
    int b  = blockIdx.z;
    int m0 = blockIdx.y * 128;
    int pt = blockIdx.x * 128;
    int e  = g_expert[b];
    float wgt = g_weight[b];
    const float* A  = g_w3r + (size_t)e * (CC * HID) + (size_t)m0 * HID;
    const float* Bx = g_y2  + (size_t)b * HID * HW + pt;

    int low = tid & 7, kq = (tid >> 3) & 7, mh0 = tid >> 6;
    int ak0 = kq * 4, amb = mh0 * 8 + low;
    uint32_t wA0 = (((mh0 >> 1) * 4 + (kq >> 1)) * 4 + ((mh0 & 1) | ((kq & 1) << 1))) * 32 + 4 * low;
    int nt_w = lane >> 1;
    uint32_t wBp[4];
    #pragma unroll
    for (int p = 0; p < 4; p++) {
        int kl = p * 8 + wid;
        wBp[p] = ((nt_w * 4 + (kl >> 3)) * 2 + ((kl >> 2) & 1)) * 32
               + (((kl & 3) ^ (nt_w & 3)) * 8) + (lane & 1) * 4;
    }
    uint32_t sm0 = cvta_s(dsm);

    float acc[2][8][4];
    #pragma unroll
    for (int i = 0; i < 2; i++)
        #pragma unroll
        for (int j = 0; j < 8; j++)
            #pragma unroll
            for (int r = 0; r < 4; r++) acc[i][j][r] = 0.f;

    auto load_chunk = [&](int kb, uint32_t base) {
        #pragma unroll
        for (int p = 0; p < 4; p++)
            cp16(base + (wA0 + 1024 * p) * 4, A + (size_t)(amb + 32 * p) * HID + kb + ak0);
        #pragma unroll
        for (int p = 0; p < 4; p++)
            cp16(base + 16384 + wBp[p] * 4, Bx + (size_t)(kb + p * 8 + wid) * HW + lane * 4);
    };

    load_chunk(0, sm0);          cp_commit();
    load_chunk(32, sm0 + 32768); cp_commit();

    int cur = 0, pf = 2;
    for (int it = 0; it < 4; it++) {
        cp_wait_group<1>();
        __syncthreads();
        if (it + 2 < 4) load_chunk((it + 2) * 32, sm0 + pf * 32768);
        cp_commit();
        const float* sA = dsm + cur * 8192;
        mma_chunk<0>(sA, sA + 4096, warpm, warpn, lane, acc);
        cur = (cur == 2) ? 0 : cur + 1;
        pf  = (pf  == 2) ? 0 : pf  + 1;
    }

    const float* Xb = x   + (size_t)b * CC * HW;
    float*       O  = out + (size_t)b * CC * HW;
    #pragma unroll
    for (int mt2 = 0; mt2 < 2; mt2++) {
        int m_lo = m0 + warpm * 32 + mt2 * 16 + gid;
        int m_hi = m_lo + 8;
        #pragma unroll
        for (int nt2 = 0; nt2 < 8; nt2++) {
            int px = pt + warpn * 64 + nt2 * 8 + 2 * tig;
            float2 x0 = *(const float2*)(Xb + (size_t)m_lo * HW + px);
            float2 x1 = *(const float2*)(Xb + (size_t)m_hi * HW + px);
            float2 v0, v1;
            v0.x = fmaf(wgt, acc[mt2][nt2][0], x0.x);
            v0.y = fmaf(wgt, acc[mt2][nt2][1], x0.y);
            v1.x = fmaf(wgt, acc[mt2][nt2][2], x1.x);
            v1.y = fmaf(wgt, acc[mt2][nt2][3], x1.y);
            *(float2*)(O + (size_t)m_lo * HW + px) = v0;
            *(float2*)(O + (size_t)m_hi * HW + px) = v1;
        }
    }
}

// ============================================================================
extern "C" void kernel_launch(void* const* d_in, const int* in_sizes, int n_in,
                              void* d_out, int out_size) {
    const float* x   = (const float*)d_in[0];
    const float* Wr1 = (const float*)d_in[1];
    const float* br1 = (const float*)d_in[2];
    const float* Wr2 = (const float*)d_in[3];
    const float* br2 = (const float*)d_in[4];
    const float* W1  = (const float*)d_in[5];
    const float* W2  = (const float*)d_in[6];
    const float* W3  = (const float*)d_in[7];
    float* out = (float*)d_out;

    cudaFuncSetAttribute(gemm1_mma_kernel, cudaFuncAttributeMaxDynamicSharedMemorySize, 98304);
    cudaFuncSetAttribute(conv3_mma_kernel, cudaFuncAttributeMaxDynamicSharedMemorySize, 98304);
    cudaFuncSetAttribute(gemm3_mma_kernel, cudaFuncAttributeMaxDynamicSharedMemorySize, 98304);

    pool_round_kernel<<<BB * CC, 256>>>(x);
    round_all_kernel <<<(W1_F4 + W2_F4 + W3_F4 + 255) / 256, 256>>>(W1, W2, W3);
    router_kernel    <<<BB, 128>>>(Wr1, br1, Wr2, br2);
    gemm1_mma_kernel <<<dim3(32, BB), 256, 98304>>>();
    conv3_mma_kernel <<<dim3(32, BB), 256, 98304>>>();
    gemm3_mma_kernel <<<dim3(32, 2, BB), 256, 98304>>>(x, out);
}

// round 17
// speedup vs baseline: 1.0025x; 1.0012x over previous
#include <cuda_runtime.h>
#include <cstdint>

// Problem constants
#define BB  16
#define CC  256
#define HW  4096
#define EE  4
#define HID 128
#define RHD 128

// ---------------- device-global scratch (allowed; no dynamic alloc) ----------
__device__ __align__(16) float g_pooled[BB * CC];
__device__ int   g_expert[BB];
__device__ float g_weight[BB];
__device__ __align__(16) float g_y1[(size_t)BB * HID * HW];    // tf32-rounded
__device__ __align__(16) float g_y2[(size_t)BB * HID * HW];    // tf32-rounded
__device__ __align__(16) float g_xr[(size_t)BB * CC * HW];     // tf32-rounded x
__device__ __align__(16) float g_w1r[EE * HID * CC];
__device__ __align__(16) float g_w2r[EE * HID * HID * 9];
__device__ __align__(16) float g_w3r[EE * CC * HID];

__device__ __forceinline__ float to_tf32(float x) {
    float r; asm("cvt.rna.tf32.f32 %0, %1;" : "=f"(r) : "f"(x)); return r;
}

// m16n8k8 tf32 mma (arch-agnostic PTX, works on plain sm_103 target)
__device__ __forceinline__ void mma_tf32(float* d,
                                         uint32_t a0, uint32_t a1, uint32_t a2, uint32_t a3,
                                         uint32_t b0, uint32_t b1) {
    asm volatile(
        "mma.sync.aligned.m16n8k8.row.col.f32.tf32.tf32.f32 "
        "{%0,%1,%2,%3}, {%4,%5,%6,%7}, {%8,%9}, {%0,%1,%2,%3};"
        : "+f"(d[0]), "+f"(d[1]), "+f"(d[2]), "+f"(d[3])
        : "r"(a0), "r"(a1), "r"(a2), "r"(a3), "r"(b0), "r"(b1));
}

// ---------------- cp.async helpers ------------------------------------------
__device__ __forceinline__ uint32_t cvta_s(const void* p) {
    return (uint32_t)__cvta_generic_to_shared(p);
}
__device__ __forceinline__ void cp16(uint32_t dst, const void* src) {
    asm volatile("cp.async.cg.shared.global [%0], [%1], 16;" :: "r"(dst), "l"(src));
}
__device__ __forceinline__ void cp4(uint32_t dst, const void* src, uint32_t ssz) {
    asm volatile("cp.async.ca.shared.global [%0], [%1], 4, %2;" :: "r"(dst), "l"(src), "r"(ssz));
}
__device__ __forceinline__ void cp_commit()   { asm volatile("cp.async.commit_group;" ::: "memory"); }
template<int N>
__device__ __forceinline__ void cp_wait_group() {
    asm volatile("cp.async.wait_group %0;" :: "n"(N) : "memory");
}

// ============================================================================
// SMEM layouts per 32-K chunk (4096 floats each = 16 KB):
//  A word((m,k)) = ((mt*4+ks)*4 + rgA)*32 + (m&7)*4 + (k&3)
//  B word((n,k)) = ((nt*4+ks)*2 + rg)*32 + (fl ^ swz(nt)),  fl=(k&3)*8+(n&7)
//      GEMM swz = (nt&3)*8 ;  CONV swz = (nt&3) | ((nt&4)<<2)
// Triple buffer: buffer i at byte offset i*32768; B at +16384 within buffer.
// ============================================================================

template<int CONV>
__device__ __forceinline__ void mma_chunk(const float* sA, const float* sB,
                                          int warpm, int warpn, int lane,
                                          float acc[2][8][4]) {
    const int fl0 = (lane & 3) * 8 + (lane >> 2);
    #pragma unroll
    for (int ks = 0; ks < 4; ks++) {
        uint32_t a[2][4];
        #pragma unroll
        for (int mt2 = 0; mt2 < 2; mt2++) {
            const float* pa = sA + ((warpm * 2 + mt2) * 4 + ks) * 128 + lane;
            a[mt2][0] = __float_as_uint(pa[0]);
            a[mt2][1] = __float_as_uint(pa[32]);
            a[mt2][2] = __float_as_uint(pa[64]);
            a[mt2][3] = __float_as_uint(pa[96]);
        }
        // software-pipelined B fragments (one nt ahead of the MMAs)
        auto ldb = [&](int nt2, uint32_t& b0, uint32_t& b1) {
            int nt  = warpn * 8 + nt2;
            int swz = CONV ? ((nt & 3) | ((nt & 4) << 2)) : ((nt & 3) * 8);
            int fx  = fl0 ^ swz;
            const float* pb = sB + (nt * 4 + ks) * 64;
            b0 = __float_as_uint(pb[fx]);
            b1 = __float_as_uint(pb[32 + fx]);
        };
        uint32_t b0c, b1c, b0n, b1n;
        ldb(0, b0c, b1c);
        #pragma unroll
        for (int nt2 = 0; nt2 < 8; nt2++) {
            if (nt2 < 7) ldb(nt2 + 1, b0n, b1n);
            mma_tf32(acc[0][nt2], a[0][0], a[0][1], a[0][2], a[0][3], b0c, b1c);
            mma_tf32(acc[1][nt2], a[1][0], a[1][1], a[1][2], a[1][3], b0c, b1c);
            b0c = b0n; b1c = b1n;
        }
    }
}

// ============================================================================
// Kernel 1: global average pool + tf32-round x into g_xr. grid=B*C, 256 thr.
// ============================================================================
__global__ void pool_round_kernel(const float* __restrict__ x) {
    int bc = blockIdx.x;
    const float4* p = (const float4*)(x + (size_t)bc * HW);
    float4* q = (float4*)(g_xr + (size_t)bc * HW);
    float s = 0.f;
    #pragma unroll
    for (int i = threadIdx.x; i < HW / 4; i += 256) {
        float4 v = p[i];
        s += (v.x + v.y) + (v.z + v.w);
        float4 r;
        r.x = to_tf32(v.x); r.y = to_tf32(v.y); r.z = to_tf32(v.z); r.w = to_tf32(v.w);
        q[i] = r;
    }
    __shared__ float red[8];
    #pragma unroll
    for (int o = 16; o > 0; o >>= 1) s += __shfl_down_sync(0xffffffffu, s, o);
    if ((threadIdx.x & 31) == 0) red[threadIdx.x >> 5] = s;
    __syncthreads();
    if (threadIdx.x < 8) {
        s = red[threadIdx.x];
        #pragma unroll
        for (int o = 4; o > 0; o >>= 1) s += __shfl_down_sync(0xffu, s, o);
        if (threadIdx.x == 0) g_pooled[bc] = s * (1.0f / (float)HW);
    }
}

// fused tf32 rounding of all three weight tensors (float4 granularity)
#define W1_F4 (EE * HID * CC / 4)
#define W2_F4 (EE * HID * HID * 9 / 4)
#define W3_F4 (EE * CC * HID / 4)
__global__ void round_all_kernel(const float* __restrict__ W1, const float* __restrict__ W2,
                                 const float* __restrict__ W3) {
    int i = blockIdx.x * 256 + threadIdx.x;
    const float4* src; float4* dst; int j;
    if (i < W1_F4)                 { src = (const float4*)W1; dst = (float4*)g_w1r; j = i; }
    else if (i < W1_F4 + W2_F4)    { src = (const float4*)W2; dst = (float4*)g_w2r; j = i - W1_F4; }
    else                           { src = (const float4*)W3; dst = (float4*)g_w3r; j = i - W1_F4 - W2_F4; }
    float4 v = src[j];
    float4 r;
    r.x = to_tf32(v.x); r.y = to_tf32(v.y); r.z = to_tf32(v.z); r.w = to_tf32(v.w);
    dst[j] = r;
}

// ============================================================================
// Kernel 2: router MLP + softmax + top-1.  grid = B, 128 threads.
// ============================================================================
__global__ void router_kernel(const float* __restrict__ Wr1, const float* __restrict__ br1,
                              const float* __restrict__ Wr2, const float* __restrict__ br2) {
    int b = blockIdx.x;
    int t = threadIdx.x;
    __shared__ float sp[CC];
    __shared__ float sh[RHD];
    __shared__ float slog[EE];
    sp[t]       = g_pooled[b * CC + t];
    sp[t + 128] = g_pooled[b * CC + t + 128];
    __syncthreads();
    {
        float acc = br1[t];
        const float* w = Wr1 + (size_t)t * CC;
        #pragma unroll 8
        for (int c = 0; c < CC; c++) acc = fmaf(sp[c], w[c], acc);
        sh[t] = fmaxf(acc, 0.f);
    }
    __syncthreads();
    if (t < EE) {
        float l = br2[t];
        const float* w = Wr2 + (size_t)t * RHD;
        #pragma unroll 8
        for (int r = 0; r < RHD; r++) l = fmaf(sh[r], w[r], l);
        slog[t] = l;
    }
    __syncthreads();
    if (t == 0) {
        float l0 = slog[0], l1 = slog[1], l2 = slog[2], l3 = slog[3];
        float m = fmaxf(fmaxf(l0, l1), fmaxf(l2, l3));
        float e0 = __expf(l0 - m), e1 = __expf(l1 - m), e2 = __expf(l2 - m), e3 = __expf(l3 - m);
        float s = e0 + e1 + e2 + e3;
        float p[4] = {e0 / s, e1 / s, e2 / s, e3 / s};
        int idx = 0; float v = p[0];
        #pragma unroll
        for (int i = 1; i < 4; i++) { if (p[i] > v) { v = p[i]; idx = i; } }
        g_expert[b] = idx;
        g_weight[b] = v / (v + 1e-9f);
    }
}

// ============================================================================
// Kernel 3: 1x1 conv C->HID + ReLU. GEMM M=128 N=4096 K=256 (8 chunks).
// 3-stage cp.async pipeline. grid=(32, B), 256 thr, 96KB dyn smem.
// ============================================================================
__global__ __launch_bounds__(256, 2) void gemm1_mma_kernel() {
    extern __shared__ float dsm[];
    const int tid = threadIdx.x, wid = tid >> 5, lane = tid & 31;
    const int warpm = wid >> 1, warpn = wid & 1;
    const int gid = lane >> 2, tig = lane & 3;
    int b  = blockIdx.y;
    int pt = blockIdx.x * 128;
    int e  = g_expert[b];
    const float* A  = g_w1r + (size_t)e * HID * CC;
    const float* Bx = g_xr  + (size_t)b * CC * HW + pt;

    int low = tid & 7, kq = (tid >> 3) & 7, mh0 = tid >> 6;
    int ak0 = kq * 4, amb = mh0 * 8 + low;
    uint32_t wA0 = (((mh0 >> 1) * 4 + (kq >> 1)) * 4 + ((mh0 & 1) | ((kq & 1) << 1))) * 32 + 4 * low;
    int nt_w = lane >> 1;
    uint32_t wBp[4];
    #pragma unroll
    for (int p = 0; p < 4; p++) {
        int kl = p * 8 + wid;
        wBp[p] = ((nt_w * 4 + (kl >> 3)) * 2 + ((kl >> 2) & 1)) * 32
               + (((kl & 3) ^ (nt_w & 3)) * 8) + (lane & 1) * 4;
    }
    uint32_t sm0 = cvta_s(dsm);

    float acc[2][8][4];
    #pragma unroll
    for (int i = 0; i < 2; i++)
        #pragma unroll
        for (int j = 0; j < 8; j++)
            #pragma unroll
            for (int r = 0; r < 4; r++) acc[i][j][r] = 0.f;

    auto load_chunk = [&](int kb, uint32_t base) {
        #pragma unroll
        for (int p = 0; p < 4; p++)
            cp16(base + (wA0 + 1024 * p) * 4, A + (size_t)(amb + 32 * p) * CC + kb + ak0);
        #pragma unroll
        for (int p = 0; p < 4; p++)
            cp16(base + 16384 + wBp[p] * 4, Bx + (size_t)(kb + p * 8 + wid) * HW + lane * 4);
    };

    load_chunk(0, sm0);       cp_commit();
    load_chunk(32, sm0 + 32768); cp_commit();

    int cur = 0, pf = 2;
    for (int it = 0; it < 8; it++) {
        cp_wait_group<1>();
        __syncthreads();
        if (it + 2 < 8) load_chunk((it + 2) * 32, sm0 + pf * 32768);
        cp_commit();     // empty group at the tail keeps wait_group semantics
        const float* sA = dsm + cur * 8192;
        mma_chunk<0>(sA, sA + 4096, warpm, warpn, lane, acc);
        cur = (cur == 2) ? 0 : cur + 1;
        pf  = (pf  == 2) ? 0 : pf  + 1;
    }

    float* Y = g_y1 + (size_t)b * HID * HW;
    #pragma unroll
    for (int mt2 = 0; mt2 < 2; mt2++) {
        int oc0 = warpm * 32 + mt2 * 16 + gid;
        #pragma unroll
        for (int nt2 = 0; nt2 < 8; nt2++) {
            int px = pt + warpn * 64 + nt2 * 8 + 2 * tig;
            float2 v0, v1;
            v0.x = to_tf32(fmaxf(acc[mt2][nt2][0], 0.f));
            v0.y = to_tf32(fmaxf(acc[mt2][nt2][1], 0.f));
            v1.x = to_tf32(fmaxf(acc[mt2][nt2][2], 0.f));
            v1.y = to_tf32(fmaxf(acc[mt2][nt2][3], 0.f));
            *(float2*)(Y + (size_t)oc0 * HW + px)       = v0;
            *(float2*)(Y + (size_t)(oc0 + 8) * HW + px) = v1;
        }
    }
}

// ============================================================================
// Kernel 4: 3x3 conv HID->HID + ReLU, implicit GEMM, K=1152 (36 chunks).
// 3-stage cp.async pipeline. grid=(32, B), 256 thr, 96KB dyn smem.
// ============================================================================
__global__ __launch_bounds__(256, 2) void conv3_mma_kernel() {
    extern __shared__ float dsm[];
    const int tid = threadIdx.x, wid = tid >> 5, lane = tid & 31;
    const int warpm = wid >> 1, warpn = wid & 1;
    const int gid = lane >> 2, tig = lane & 3;
    int b  = blockIdx.y;
    int pb = blockIdx.x;
    int pbase = pb << 7;
    int y0 = pb << 1;
    int e  = g_expert[b];
    const float* A  = g_w2r + (size_t)e * (HID * HID * 9);  // [128][1152]
    const float* Y1 = g_y1 + (size_t)b * HID * HW;

    int low = tid & 7, kq = (tid >> 3) & 7, mh0 = tid >> 6;
    int ak0 = kq * 4, amb = mh0 * 8 + low;
    uint32_t wA0 = (((mh0 >> 1) * 4 + (kq >> 1)) * 4 + ((mh0 & 1) | ((kq & 1) << 1))) * 32 + 4 * low;
    int nqL = lane & 15, kbit = lane >> 4;
    int klp[4], col0p[4], rowp[4], s01p[4];
    uint32_t wB0p[4];
    #pragma unroll
    for (int p = 0; p < 4; p++) {
        int kl = 2 * wid + kbit + 16 * (p & 1);
        int nq = nqL + 16 * (p >> 1);
        int n0 = nq * 4;
        int nt = nq >> 1;
        klp[p]   = kl;
        col0p[p] = n0 & 63;
        rowp[p]  = n0 >> 6;
        s01p[p]  = nt & 3;
        int fl0p = (kl & 3) * 8 + (nq & 1) * 4;
        wB0p[p]  = ((nt * 4 + (kl >> 3)) * 2 + ((kl >> 2) & 1)) * 32
                 + (fl0p ^ ((nt & 4) << 2));
    }
    uint32_t sm0 = cvta_s(dsm);

    float acc[2][8][4];
    #pragma unroll
    for (int i = 0; i < 2; i++)
        #pragma unroll
        for (int j = 0; j < 8; j++)
            #pragma unroll
            for (int r = 0; r < 4; r++) acc[i][j][r] = 0.f;

    auto load_chunk = [&](int kb, uint32_t base) {
        #pragma unroll
        for (int p = 0; p < 4; p++)
            cp16(base + (wA0 + 1024 * p) * 4, A + (size_t)(amb + 32 * p) * 1152 + kb + ak0);
        uint32_t bB = base + 16384;
        #pragma unroll
        for (int p = 0; p < 4; p++) {
            int k   = kb + klp[p];
            int ic  = k / 9;
            int tap = k - ic * 9;
            int ky  = tap / 3;
            int dx  = tap - ky * 3 - 1;
            int gy  = y0 + rowp[p] + ky - 1;
            bool vy = ((unsigned)gy < 64u);
            const float* srow = Y1 + (size_t)ic * HW + (gy << 6);
            #pragma unroll
            for (int j = 0; j < 4; j++) {
                int gx  = col0p[p] + j + dx;
                bool ok = vy & ((unsigned)gx < 64u);
                cp4(bB + (wB0p[p] + (j ^ s01p[p])) * 4, ok ? (srow + gx) : Y1, ok ? 4u : 0u);
            }
        }
    };

    load_chunk(0, sm0);          cp_commit();
    load_chunk(32, sm0 + 32768); cp_commit();

    int cur = 0, pf = 2;
    for (int it = 0; it < 36; it++) {
        cp_wait_group<1>();
        __syncthreads();
        if (it + 2 < 36) load_chunk((it + 2) * 32, sm0 + pf * 32768);
        cp_commit();
        const float* sA = dsm + cur * 8192;
        mma_chunk<1>(sA, sA + 4096, warpm, warpn, lane, acc);
        cur = (cur == 2) ? 0 : cur + 1;
        pf  = (pf  == 2) ? 0 : pf  + 1;
    }

    float* Y2 = g_y2 + (size_t)b * HID * HW;
    #pragma unroll
    for (int mt2 = 0; mt2 < 2; mt2++) {
        int oc0 = warpm * 32 + mt2 * 16 + gid;
        #pragma unroll
        for (int nt2 = 0; nt2 < 8; nt2++) {
            int px = pbase + warpn * 64 + nt2 * 8 + 2 * tig;
            float2 v0, v1;
            v0.x = to_tf32(fmaxf(acc[mt2][nt2][0], 0.f));
            v0.y = to_tf32(fmaxf(acc[mt2][nt2][1], 0.f));
            v1.x = to_tf32(fmaxf(acc[mt2][nt2][2], 0.f));
            v1.y = to_tf32(fmaxf(acc[mt2][nt2][3], 0.f));
            *(float2*)(Y2 + (size_t)oc0 * HW + px)       = v0;
            *(float2*)(Y2 + (size_t)(oc0 + 8) * HW + px) = v1;
        }
    }
}

// ============================================================================
// Kernel 5: 1x1 conv HID->C * wgt + residual. GEMM M=256 N=4096 K=128.
// 3-stage cp.async pipeline. grid=(32, 2, B), 256 thr, 96KB dyn smem.
// ============================================================================
__global__ __launch_bounds__(256, 2) void gemm3_mma_kernel(const float* __restrict__ x,
                                                           float* __restrict__ out) {
    extern __shared__ float dsm[];
    const int tid = threadIdx.x, wid = tid >> 5, lane = tid & 31;
    const int warpm = wid >> 1, warpn = wid & 1;
    const int gid = lane >> 2, tig = lane & 3;
    int b  = blockIdx.z;
    int m0 = blockIdx.y * 128;
    int pt = blockIdx.x * 128;
    int e  = g_expert[b];
    float wgt = g_weight[b];
    const float* A  = g_w3r + (size_t)e * (CC * HID) + (size_t)m0 * HID;
    const float* Bx = g_y2  + (size_t)b * HID * HW + pt;

    int low = tid & 7, kq = (tid >> 3) & 7, mh0 = tid >> 6;
    int ak0 = kq * 4, amb = mh0 * 8 + low;
    uint32_t wA0 = (((mh0 >> 1) * 4 + (kq >> 1)) * 4 + ((mh0 & 1) | ((kq & 1) << 1))) * 32 + 4 * low;
    int nt_w = lane >> 1;
    uint32_t wBp[4];
    #pragma unroll
    for (int p = 0; p < 4; p++) {
        int kl = p * 8 + wid;
        wBp[p] = ((nt_w * 4 + (kl >> 3)) * 2 + ((kl >> 2) & 1)) * 32
               + (((kl & 3) ^ (nt_w & 3)) * 8) + (lane & 1) * 4;
    }
    uint32_t sm0 = cvta_s(dsm);

    float acc[2][8][4];
    #pragma unroll
    for (int i = 0; i < 2; i++)
        #pragma unroll
        for (int j = 0; j < 8; j++)
            #pragma unroll
            for (int r = 0; r < 4; r++) acc[i][j][r] = 0.f;

    auto load_chunk = [&](int kb, uint32_t base) {
        #pragma unroll
        for (int p = 0; p < 4; p++)
            cp16(base + (wA0 + 1024 * p) * 4, A + (size_t)(amb + 32 * p) * HID + kb + ak0);
        #pragma unroll
        for (int p = 0; p < 4; p++)
            cp16(base + 16384 + wBp[p] * 4, Bx + (size_t)(kb + p * 8 + wid) * HW + lane * 4);
    };

    load_chunk(0, sm0);          cp_commit();
    load_chunk(32, sm0 + 32768); cp_commit();

    int cur = 0, pf = 2;
    for (int it = 0; it < 4; it++) {
        cp_wait_group<1>();
        __syncthreads();
        if (it + 2 < 4) load_chunk((it + 2) * 32, sm0 + pf * 32768);
        cp_commit();
        const float* sA = dsm + cur * 8192;
        mma_chunk<0>(sA, sA + 4096, warpm, warpn, lane, acc);
        cur = (cur == 2) ? 0 : cur + 1;
        pf  = (pf  == 2) ? 0 : pf  + 1;
    }

    const float* Xb = x   + (size_t)b * CC * HW;
    float*       O  = out + (size_t)b * CC * HW;
    #pragma unroll
    for (int mt2 = 0; mt2 < 2; mt2++) {
        int m_lo = m0 + warpm * 32 + mt2 * 16 + gid;
        int m_hi = m_lo + 8;
        #pragma unroll
        for (int nt2 = 0; nt2 < 8; nt2++) {
            int px = pt + warpn * 64 + nt2 * 8 + 2 * tig;
            float2 x0 = *(const float2*)(Xb + (size_t)m_lo * HW + px);
            float2 x1 = *(const float2*)(Xb + (size_t)m_hi * HW + px);
            float2 v0, v1;
            v0.x = fmaf(wgt, acc[mt2][nt2][0], x0.x);
            v0.y = fmaf(wgt, acc[mt2][nt2][1], x0.y);
            v1.x = fmaf(wgt, acc[mt2][nt2][2], x1.x);
            v1.y = fmaf(wgt, acc[mt2][nt2][3], x1.y);
            *(float2*)(O + (size_t)m_lo * HW + px) = v0;
            *(float2*)(O + (size_t)m_hi * HW + px) = v1;
        }
    }
}

// ============================================================================
extern "C" void kernel_launch(void* const* d_in, const int* in_sizes, int n_in,
                              void* d_out, int out_size) {
    const float* x   = (const float*)d_in[0];
    const float* Wr1 = (const float*)d_in[1];
    const float* br1 = (const float*)d_in[2];
    const float* Wr2 = (const float*)d_in[3];
    const float* br2 = (const float*)d_in[4];
    const float* W1  = (const float*)d_in[5];
    const float* W2  = (const float*)d_in[6];
    const float* W3  = (const float*)d_in[7];
    float* out = (float*)d_out;

    cudaFuncSetAttribute(gemm1_mma_kernel, cudaFuncAttributeMaxDynamicSharedMemorySize, 98304);
    cudaFuncSetAttribute(conv3_mma_kernel, cudaFuncAttributeMaxDynamicSharedMemorySize, 98304);
    cudaFuncSetAttribute(gemm3_mma_kernel, cudaFuncAttributeMaxDynamicSharedMemorySize, 98304);

    pool_round_kernel<<<BB * CC, 256>>>(x);
    round_all_kernel <<<(W1_F4 + W2_F4 + W3_F4 + 255) / 256, 256>>>(W1, W2, W3);
    router_kernel    <<<BB, 128>>>(Wr1, br1, Wr2, br2);
    gemm1_mma_kernel <<<dim3(32, BB), 256, 98304>>>();
    conv3_mma_kernel <<<dim3(32, BB), 256, 98304>>>();
    gemm3_mma_kernel <<<dim3(32, 2, BB), 256, 98304>>>(x, out);
}